// round 12
// baseline (speedup 1.0000x reference)
#include <cuda_runtime.h>
#include <cuda_bf16.h>
#include <math.h>

#define BB 4
#define SS 2048
#define HH 1024
#define NH 16
#define HD 64
#define MM (BB*SS)          // 8192 rows

// ---------------- scratch (device globals; no allocation allowed) ----------
__device__ __nv_bfloat16 g_y[BB*SS*HH];        // LN output        16 MB
__device__ __nv_bfloat16 g_q[BB*NH*SS*HD];     // Q [b,h,s,d]      16 MB
__device__ __nv_bfloat16 g_k[BB*NH*SS*HD];     // K [b,h,s,d]      16 MB
__device__ __nv_bfloat16 g_v[BB*NH*SS*HD];     // V [b,h,s,d]      16 MB
__device__ __nv_bfloat16 g_ctx[BB*SS*HH];      // attention ctx    16 MB
__device__ __nv_bfloat16 g_wq[3*HH*HH];        // bf16 qkv weights  6 MB
__device__ __nv_bfloat16 g_wo[HH*HH];          // bf16 out weights  2 MB

// ---------------- helpers ---------------------------------------------------
__device__ __forceinline__ unsigned pkbf(float lo, float hi) {
    __nv_bfloat162 h = __float22bfloat162_rn(make_float2(lo, hi));
    return *(unsigned*)&h;
}
__device__ __forceinline__ void mma_bf16(float* d, const unsigned* a, const unsigned* b) {
    asm("mma.sync.aligned.m16n8k16.row.col.f32.bf16.bf16.f32 "
        "{%0,%1,%2,%3},{%4,%5,%6,%7},{%8,%9},{%0,%1,%2,%3};"
        : "+f"(d[0]), "+f"(d[1]), "+f"(d[2]), "+f"(d[3])
        : "r"(a[0]), "r"(a[1]), "r"(a[2]), "r"(a[3]), "r"(b[0]), "r"(b[1]));
}
__device__ __forceinline__ void ldsm_x4(unsigned* r, unsigned addr) {
    asm volatile("ldmatrix.sync.aligned.m8n8.x4.shared.b16 {%0,%1,%2,%3},[%4];"
        : "=r"(r[0]), "=r"(r[1]), "=r"(r[2]), "=r"(r[3]) : "r"(addr));
}
__device__ __forceinline__ void ldsm_x4t(unsigned* r, unsigned addr) {
    asm volatile("ldmatrix.sync.aligned.m8n8.x4.trans.shared.b16 {%0,%1,%2,%3},[%4];"
        : "=r"(r[0]), "=r"(r[1]), "=r"(r[2]), "=r"(r[3]) : "r"(addr));
}
__device__ __forceinline__ void cpa16(unsigned dst, const void* src) {
    asm volatile("cp.async.cg.shared.global [%0], [%1], 16;" :: "r"(dst), "l"(src));
}
__device__ __forceinline__ void cpa_commit() {
    asm volatile("cp.async.commit_group;" ::: "memory");
}
template<int N> __device__ __forceinline__ void cpa_wait() {
    asm volatile("cp.async.wait_group %0;" :: "n"(N) : "memory");
}
__device__ __forceinline__ float ex2(float x) {
    float r; asm("ex2.approx.f32 %0, %1;" : "=f"(r) : "f"(x)); return r;
}

// ======================= 0) weight convert (f32 -> bf16) ===================
__global__ void __launch_bounds__(256) wcvt_kernel(
    const float* __restrict__ qw, const float* __restrict__ ow)
{
    const int NQ = 3*HH*HH;
    int i4 = (blockIdx.x*256 + threadIdx.x) * 4;
    if (i4 < NQ) {
        float4 v = *(const float4*)(qw + i4);
        uint2 o; o.x = pkbf(v.x, v.y); o.y = pkbf(v.z, v.w);
        *(uint2*)(g_wq + i4) = o;
    } else {
        float4 v = *(const float4*)(ow + (i4 - NQ));
        uint2 o; o.x = pkbf(v.x, v.y); o.y = pkbf(v.z, v.w);
        *(uint2*)(g_wo + (i4 - NQ)) = o;
    }
}

// ======================= 1) LayerNorm (f32 in -> bf16 out) =================
__global__ void __launch_bounds__(256) ln_kernel(
    const float* __restrict__ x,
    const float* __restrict__ gamma,
    const float* __restrict__ beta)
{
    int row = blockIdx.x;
    int tid = threadIdx.x;
    const float4 xv = *(const float4*)&x[row*HH + tid*4];

    float s  = xv.x + xv.y + xv.z + xv.w;
    float s2 = xv.x*xv.x + xv.y*xv.y + xv.z*xv.z + xv.w*xv.w;
    #pragma unroll
    for (int o = 16; o > 0; o >>= 1) {
        s  += __shfl_down_sync(0xffffffffu, s,  o);
        s2 += __shfl_down_sync(0xffffffffu, s2, o);
    }
    __shared__ float ss[8], ss2[8];
    if ((tid & 31) == 0) { ss[tid >> 5] = s; ss2[tid >> 5] = s2; }
    __syncthreads();
    float ts = 0.f, ts2 = 0.f;
    #pragma unroll
    for (int w = 0; w < 8; w++) { ts += ss[w]; ts2 += ss2[w]; }

    float mu   = ts * (1.0f / HH);
    float var  = ts2 * (1.0f / HH) - mu * mu;
    float rstd = rsqrtf(var + 1e-5f);

    const float4 gv = *(const float4*)&gamma[tid*4];
    const float4 bv = *(const float4*)&beta[tid*4];
    uint2 o2;
    o2.x = pkbf((xv.x - mu)*rstd*gv.x + bv.x, (xv.y - mu)*rstd*gv.y + bv.y);
    o2.y = pkbf((xv.z - mu)*rstd*gv.z + bv.z, (xv.w - mu)*rstd*gv.w + bv.w);
    *(uint2*)&g_y[row*HH + tid*4] = o2;
}

// ======================= bf16 GEMM (128x128, 8 warps, 64x32 warp tile) =====
// 3-stage cp.async pipeline, k-step 32; both operands bf16 in gmem.
// acc = 64 regs/thread -> <=128 regs -> 2 CTAs/SM (16 warps) via launch_bounds.
#define GST      40               // halves; 80B = odd multiple of 16B
#define STAGE_H  (128*GST)        // 5120 halves per operand per stage
#define GSMEM_H  (2*STAGE_H)      // A+B per stage
#define GEMM_SMEM (3*GSMEM_H*2)   // 61440 B

// 256 threads: thread -> row (tid>>1) of A and B, 32B chunk (tid&1)
#define GEMM_PREFETCH(kt) do {                                              \
    int s_ = (kt) % 3;                                                      \
    int r_ = tid >> 1;                                                      \
    int h_ = (tid & 1) * 16;                                                \
    unsigned aDst = dsmB + (unsigned)((s_*GSMEM_H + r_*GST + h_) * 2);      \
    unsigned bDst = aDst + STAGE_H*2;                                       \
    const __nv_bfloat16* a_ = Ag + (size_t)r_*HH + (kt)*32 + h_;            \
    const __nv_bfloat16* b_ = Bg + (size_t)r_*HH + (kt)*32 + h_;            \
    cpa16(aDst,      a_);                                                   \
    cpa16(aDst + 16, a_ + 8);                                               \
    cpa16(bDst,      b_);                                                   \
    cpa16(bDst + 16, b_ + 8);                                               \
} while (0)

#define GEMM_MAINLOOP(ACC)                                                  \
    GEMM_PREFETCH(0); cpa_commit();                                         \
    GEMM_PREFETCH(1); cpa_commit();                                         \
    const unsigned aOff = (unsigned)(((warp_m + (lane & 15))*GST + (lane >> 4)*8) * 2);            \
    const unsigned bOff = (unsigned)(((warp_n + (lane >> 4)*8 + (lane & 7))*GST + ((lane >> 3) & 1)*8) * 2) + STAGE_H*2; \
    for (int kt = 0; kt < 32; kt++) {                                       \
        cpa_wait<1>();                                                      \
        __syncthreads();                                                    \
        if (kt + 2 < 32) { GEMM_PREFETCH(kt + 2); }                         \
        cpa_commit();                                                       \
        unsigned sB = dsmB + (unsigned)((kt % 3)*GSMEM_H*2);                \
        _Pragma("unroll")                                                   \
        for (int kc = 0; kc < 2; kc++) {                                    \
            unsigned af[4][4], bf[2][4];                                    \
            _Pragma("unroll")                                               \
            for (int mt = 0; mt < 4; mt++)                                  \
                ldsm_x4(af[mt], sB + aOff + (unsigned)((mt*16*GST + kc*16)*2)); \
            _Pragma("unroll")                                               \
            for (int np = 0; np < 2; np++)                                  \
                ldsm_x4(bf[np], sB + bOff + (unsigned)((np*16*GST + kc*16)*2)); \
            _Pragma("unroll")                                               \
            for (int mt = 0; mt < 4; mt++)                                  \
                _Pragma("unroll")                                           \
                for (int np = 0; np < 2; np++) {                            \
                    mma_bf16(ACC[mt][2*np],   af[mt], &bf[np][0]);          \
                    mma_bf16(ACC[mt][2*np+1], af[mt], &bf[np][2]);          \
                }                                                           \
        }                                                                   \
    }

// ---- QKV GEMM: epilogue scatters bf16 to g_q/g_k/g_v [b,h,s,d] ------------
__global__ void __launch_bounds__(256, 2) gemm_qkv_kernel(const float* __restrict__ bias)
{
    extern __shared__ __nv_bfloat16 dsm[];
    const int tid = threadIdx.x, lane = tid & 31, w = tid >> 5;
    const int warp_m = (w >> 2) * 64, warp_n = (w & 3) * 32;
    const int n0 = blockIdx.x * 128, m0 = blockIdx.y * 128;
    const __nv_bfloat16* Ag = g_y  + (size_t)m0 * HH;
    const __nv_bfloat16* Bg = g_wq + (size_t)n0 * HH;
    const unsigned dsmB = (unsigned)__cvta_generic_to_shared(dsm);

    float acc[4][4][4] = {};
    GEMM_MAINLOOP(acc)

    const int g = lane >> 2, t2 = (lane & 3) * 2;
    #pragma unroll
    for (int nt = 0; nt < 4; nt++) {
        int gn = n0 + warp_n + nt*8 + t2;
        int grp = gn >> 10, head = (gn >> 6) & 15, d = gn & 63;
        __nv_bfloat16* dst = (grp == 0) ? g_q : (grp == 1) ? g_k : g_v;
        float2 bi = *(const float2*)&bias[gn];
        #pragma unroll
        for (int mt = 0; mt < 4; mt++) {
            int m = m0 + warp_m + mt*16 + g;
            int b = m >> 11, s = m & 2047;
            __nv_bfloat16* p = &dst[((size_t)(b*NH + head)*SS + s)*HD + d];
            *(unsigned*)p          = pkbf(acc[mt][nt][0] + bi.x, acc[mt][nt][1] + bi.y);
            *(unsigned*)(p + 8*HD) = pkbf(acc[mt][nt][2] + bi.x, acc[mt][nt][3] + bi.y);
        }
    }
}

// ---- Output GEMM: + bias + residual (f32 out) -----------------------------
__global__ void __launch_bounds__(256, 2) gemm_out_kernel(
    const float* __restrict__ bias,
    const float* __restrict__ x,
    float* __restrict__ out)
{
    extern __shared__ __nv_bfloat16 dsm[];
    const int tid = threadIdx.x, lane = tid & 31, w = tid >> 5;
    const int warp_m = (w >> 2) * 64, warp_n = (w & 3) * 32;
    const int n0 = blockIdx.x * 128, m0 = blockIdx.y * 128;
    const __nv_bfloat16* Ag = g_ctx + (size_t)m0 * HH;
    const __nv_bfloat16* Bg = g_wo  + (size_t)n0 * HH;
    const unsigned dsmB = (unsigned)__cvta_generic_to_shared(dsm);

    float acc[4][4][4] = {};
    GEMM_MAINLOOP(acc)

    const int g = lane >> 2, t2 = (lane & 3) * 2;
    #pragma unroll
    for (int nt = 0; nt < 4; nt++) {
        int gn = n0 + warp_n + nt*8 + t2;
        float2 bi = *(const float2*)&bias[gn];
        #pragma unroll
        for (int mt = 0; mt < 4; mt++) {
            int m = m0 + warp_m + mt*16 + g;
            const float2 x0 = *(const float2*)&x[(size_t)m*HH + gn];
            const float2 x1 = *(const float2*)&x[(size_t)(m+8)*HH + gn];
            float2 v0 = {acc[mt][nt][0] + bi.x + x0.x, acc[mt][nt][1] + bi.y + x0.y};
            float2 v1 = {acc[mt][nt][2] + bi.x + x1.x, acc[mt][nt][3] + bi.y + x1.y};
            *(float2*)&out[(size_t)m*HH + gn]     = v0;
            *(float2*)&out[(size_t)(m+8)*HH + gn] = v1;
        }
    }
}

// ======================= 3) Flash attention (bf16 mma, pipelined) ==========
// 256 threads (8 warps); q-tile 128 (16 rows/warp), k-tile 64.
// Cross-tile pipeline: QK(t+1) issued between softmax(t) and PV(t) so
// tensor work and MUFU(ex2) work from different warps overlap.
// 3-stage cp.async K/V ring (K(t+1) + V(t) live while prefetch(t+2) lands).
#define AST 72
#define ATT_KV_H   (64*AST)
#define ATT_K_OFF  (128*AST)
#define ATT_V_OFF  (128*AST + 3*ATT_KV_H)
#define ATT_SMEM   ((128*AST + 6*ATT_KV_H)*2)   // 73728 B
#define LOG2E 1.44269504f
#define NTILES (SS/64)                           // 32

#define ATT_PREFETCH(it) do {                                               \
    int s_ = (it) % 3;                                                      \
    int r_ = tid >> 2;                                                      \
    int ch_ = (tid & 3) * 2;                                                \
    unsigned kDst = base + (unsigned)((ATT_K_OFF + s_*ATT_KV_H + r_*AST)*2); \
    unsigned vDst = base + (unsigned)((ATT_V_OFF + s_*ATT_KV_H + r_*AST)*2); \
    const __nv_bfloat16* kp = Kg + (size_t)((it)*64 + r_)*HD;               \
    const __nv_bfloat16* vp = Vg + (size_t)((it)*64 + r_)*HD;               \
    _Pragma("unroll")                                                       \
    for (int c_ = 0; c_ < 2; c_++) {                                        \
        cpa16(kDst + (ch_ + c_)*16, kp + (ch_ + c_)*8);                     \
        cpa16(vDst + (ch_ + c_)*16, vp + (ch_ + c_)*8);                     \
    }                                                                       \
    if (tid < 64) ms3[s_][tid] = -1e8f*LOG2E * (float)mg[(it)*64 + tid];    \
} while (0)

#define ATT_QK(it) do {                                                     \
    const unsigned kS_ = base + (unsigned)((ATT_K_OFF + ((it)%3)*ATT_KV_H)*2); \
    _Pragma("unroll")                                                       \
    for (int nt_ = 0; nt_ < 8; nt_++)                                       \
        _Pragma("unroll")                                                   \
        for (int j_ = 0; j_ < 4; j_++) ss[nt_][j_] = 0.f;                   \
    _Pragma("unroll")                                                       \
    for (int dc_ = 0; dc_ < 4; dc_++)                                       \
        _Pragma("unroll")                                                   \
        for (int np_ = 0; np_ < 4; np_++) {                                 \
            unsigned bk_[4];                                                \
            ldsm_x4(bk_, kS_ + kOff + (unsigned)((np_*16*AST + dc_*16)*2)); \
            mma_bf16(ss[2*np_],   qf[dc_], &bk_[0]);                        \
            mma_bf16(ss[2*np_+1], qf[dc_], &bk_[2]);                        \
        }                                                                   \
} while (0)

__global__ void __launch_bounds__(256, 2) attn_kernel(const int* __restrict__ mask)
{
    extern __shared__ __nv_bfloat16 smp[];
    __shared__ float ms3[3][64];

    const int tid  = threadIdx.x;
    const int lane = tid & 31;
    const int w    = tid >> 5;
    const int bh = blockIdx.y;
    const int q0 = blockIdx.x * 128;
    const int b  = bh >> 4, h = bh & 15;

    const __nv_bfloat16* Qg = g_q + (size_t)bh * SS * HD;
    const __nv_bfloat16* Kg = g_k + (size_t)bh * SS * HD;
    const __nv_bfloat16* Vg = g_v + (size_t)bh * SS * HD;
    const int*           mg = mask + b * SS;

    const unsigned base = (unsigned)__cvta_generic_to_shared(smp);

    // stage Q (bf16 copy) + prefetch K/V tiles 0,1
    {
        int r = tid >> 1, c0 = (tid & 1) * 32;
        #pragma unroll
        for (int i = 0; i < 4; i++)
            *(uint4*)&smp[r*AST + c0 + i*8] =
                *(const uint4*)&Qg[(size_t)(q0 + r)*HD + c0 + i*8];
    }
    ATT_PREFETCH(0); cpa_commit();
    ATT_PREFETCH(1); cpa_commit();
    cpa_wait<1>(); __syncthreads();   // tile 0 ready; Q staged

    // cache Q fragments (4 d-chunks)
    const unsigned qBase = base + (unsigned)(((w*16 + (lane & 15))*AST + (lane >> 4)*8) * 2);
    unsigned qf[4][4];
    #pragma unroll
    for (int dc = 0; dc < 4; dc++)
        ldsm_x4(qf[dc], qBase + (unsigned)(dc*16*2));

    const unsigned kOff = (unsigned)((((lane >> 4)*8 + (lane & 7))*AST + ((lane >> 3) & 1)*8) * 2);
    const unsigned vOff = (unsigned)(((((lane >> 3) & 1)*8 + (lane & 7))*AST + (lane >> 4)*8) * 2);

    float o[8][4] = {};
    float lrun0 = 0.f, lrun1 = 0.f;
    const int t2 = (lane & 3) * 2;
    const float SC2 = 0.125f * LOG2E;

    float ss[8][4];
    ATT_QK(0);                        // S(0) before the loop

    for (int it = 0; it < NTILES; it++) {
        if (it + 2 < NTILES) { ATT_PREFETCH(it + 2); }
        cpa_commit();

        // ---- softmax(it): ss -> packed P (ap) + per-lane sums -------------
        unsigned ap[4][4];
        const float* msp = ms3[it % 3];
        #pragma unroll
        for (int nt = 0; nt < 8; nt++) {
            float b0 = msp[nt*8 + t2], b1 = msp[nt*8 + t2 + 1];
            float p0 = ex2(ss[nt][0]*SC2 + b0);
            float p1 = ex2(ss[nt][1]*SC2 + b1);
            float p2 = ex2(ss[nt][2]*SC2 + b0);
            float p3 = ex2(ss[nt][3]*SC2 + b1);
            lrun0 += p0 + p1;
            lrun1 += p2 + p3;
            ap[nt >> 1][(nt & 1)*2]     = pkbf(p0, p1);
            ap[nt >> 1][(nt & 1)*2 + 1] = pkbf(p2, p3);
        }

        // ---- QK(it+1): independent of P, overlaps other warps' softmax ----
        if (it + 1 < NTILES) {
            cpa_wait<1>(); __syncthreads();   // tile it+1 K/V ready
            ATT_QK(it + 1);
        }

        // ---- PV(it) -------------------------------------------------------
        {
            const unsigned vS = base + (unsigned)((ATT_V_OFF + (it % 3)*ATT_KV_H)*2);
            #pragma unroll
            for (int kc = 0; kc < 4; kc++)
                #pragma unroll
                for (int p = 0; p < 4; p++) {
                    unsigned bv[4];
                    ldsm_x4t(bv, vS + vOff + (unsigned)((kc*16*AST + p*16)*2));
                    mma_bf16(o[2*p],   ap[kc], &bv[0]);
                    mma_bf16(o[2*p+1], ap[kc], &bv[2]);
                }
        }
        __syncthreads();   // stage it%3 free for prefetch(it+3) next iter
    }

    // epilogue: single cross-lane sum reduction, then normalize + store
    lrun0 += __shfl_xor_sync(0xffffffffu, lrun0, 1);
    lrun0 += __shfl_xor_sync(0xffffffffu, lrun0, 2);
    lrun1 += __shfl_xor_sync(0xffffffffu, lrun1, 1);
    lrun1 += __shfl_xor_sync(0xffffffffu, lrun1, 2);
    float inv0 = 1.0f / lrun0, inv1 = 1.0f / lrun1;
    int r0 = q0 + w*16 + (lane >> 2);
    #pragma unroll
    for (int dt = 0; dt < 8; dt++) {
        int d = dt*8 + t2;
        *(unsigned*)&g_ctx[((size_t)b*SS + r0)*HH + h*HD + d] =
            pkbf(o[dt][0]*inv0, o[dt][1]*inv0);
        *(unsigned*)&g_ctx[((size_t)b*SS + r0 + 8)*HH + h*HD + d] =
            pkbf(o[dt][2]*inv1, o[dt][3]*inv1);
    }
}

// ======================= launch ============================================
extern "C" void kernel_launch(void* const* d_in, const int* in_sizes, int n_in,
                              void* d_out, int out_size)
{
    const float* x      = (const float*)d_in[0];
    const int*   mask   = (const int*)  d_in[1];
    const float* qkv_w  = (const float*)d_in[2];
    const float* qkv_b  = (const float*)d_in[3];
    const float* out_w  = (const float*)d_in[4];
    const float* out_b  = (const float*)d_in[5];
    const float* gamma  = (const float*)d_in[6];
    const float* beta   = (const float*)d_in[7];
    float* out = (float*)d_out;

    cudaFuncSetAttribute(gemm_qkv_kernel,
                         cudaFuncAttributeMaxDynamicSharedMemorySize, GEMM_SMEM);
    cudaFuncSetAttribute(gemm_out_kernel,
                         cudaFuncAttributeMaxDynamicSharedMemorySize, GEMM_SMEM);
    cudaFuncSetAttribute(attn_kernel,
                         cudaFuncAttributeMaxDynamicSharedMemorySize, ATT_SMEM);

    // 0) weights -> bf16 (4M elements, 4/thread)
    wcvt_kernel<<<4096, 256>>>(qkv_w, out_w);

    // 1) LayerNorm (f32 -> bf16)
    ln_kernel<<<MM, 256>>>(x, gamma, beta);

    // 2) QKV projection: N=3072, M=8192
    gemm_qkv_kernel<<<dim3(3*HH/128, MM/128), 256, GEMM_SMEM>>>(qkv_b);

    // 3) attention: 16 q-tiles x 64 (b,h)
    attn_kernel<<<dim3(SS/128, BB*NH), 256, ATT_SMEM>>>(mask);

    // 4) output projection + bias + residual
    gemm_out_kernel<<<dim3(HH/128, MM/128), 256, GEMM_SMEM>>>(out_b, x, out);
}

// round 14
// speedup vs baseline: 1.2715x; 1.2715x over previous
#include <cuda_runtime.h>
#include <cuda_bf16.h>
#include <math.h>

#define BB 4
#define SS 2048
#define HH 1024
#define NH 16
#define HD 64
#define MM (BB*SS)          // 8192 rows

// ---------------- scratch (device globals; no allocation allowed) ----------
__device__ __nv_bfloat16 g_y[BB*SS*HH];        // LN output        16 MB
__device__ __nv_bfloat16 g_q[BB*NH*SS*HD];     // Q [b,h,s,d]      16 MB
__device__ __nv_bfloat16 g_k[BB*NH*SS*HD];     // K [b,h,s,d]      16 MB
__device__ __nv_bfloat16 g_v[BB*NH*SS*HD];     // V [b,h,s,d]      16 MB
__device__ __nv_bfloat16 g_ctx[BB*SS*HH];      // attention ctx    16 MB
__device__ __nv_bfloat16 g_wq[3*HH*HH];        // bf16 qkv weights  6 MB
__device__ __nv_bfloat16 g_wo[HH*HH];          // bf16 out weights  2 MB
__device__ int g_idx[BB*SS];                   // compacted unmasked key idx
__device__ int g_cnt[BB];                      // unmasked count per batch

// ---------------- helpers ---------------------------------------------------
__device__ __forceinline__ unsigned pkbf(float lo, float hi) {
    __nv_bfloat162 h = __float22bfloat162_rn(make_float2(lo, hi));
    return *(unsigned*)&h;
}
__device__ __forceinline__ void mma_bf16(float* d, const unsigned* a, const unsigned* b) {
    asm("mma.sync.aligned.m16n8k16.row.col.f32.bf16.bf16.f32 "
        "{%0,%1,%2,%3},{%4,%5,%6,%7},{%8,%9},{%0,%1,%2,%3};"
        : "+f"(d[0]), "+f"(d[1]), "+f"(d[2]), "+f"(d[3])
        : "r"(a[0]), "r"(a[1]), "r"(a[2]), "r"(a[3]), "r"(b[0]), "r"(b[1]));
}
__device__ __forceinline__ void ldsm_x4(unsigned* r, unsigned addr) {
    asm volatile("ldmatrix.sync.aligned.m8n8.x4.shared.b16 {%0,%1,%2,%3},[%4];"
        : "=r"(r[0]), "=r"(r[1]), "=r"(r[2]), "=r"(r[3]) : "r"(addr));
}
__device__ __forceinline__ void ldsm_x4t(unsigned* r, unsigned addr) {
    asm volatile("ldmatrix.sync.aligned.m8n8.x4.trans.shared.b16 {%0,%1,%2,%3},[%4];"
        : "=r"(r[0]), "=r"(r[1]), "=r"(r[2]), "=r"(r[3]) : "r"(addr));
}
__device__ __forceinline__ void cpa16(unsigned dst, const void* src) {
    asm volatile("cp.async.cg.shared.global [%0], [%1], 16;" :: "r"(dst), "l"(src));
}
__device__ __forceinline__ void cpa_commit() {
    asm volatile("cp.async.commit_group;" ::: "memory");
}
template<int N> __device__ __forceinline__ void cpa_wait() {
    asm volatile("cp.async.wait_group %0;" :: "n"(N) : "memory");
}
__device__ __forceinline__ float ex2(float x) {
    float r; asm("ex2.approx.f32 %0, %1;" : "=f"(r) : "f"(x)); return r;
}

// ======================= 0) weight convert (f32 -> bf16) ===================
__global__ void __launch_bounds__(256) wcvt_kernel(
    const float* __restrict__ qw, const float* __restrict__ ow)
{
    const int NQ = 3*HH*HH;
    int i4 = (blockIdx.x*256 + threadIdx.x) * 4;
    if (i4 < NQ) {
        float4 v = *(const float4*)(qw + i4);
        uint2 o; o.x = pkbf(v.x, v.y); o.y = pkbf(v.z, v.w);
        *(uint2*)(g_wq + i4) = o;
    } else {
        float4 v = *(const float4*)(ow + (i4 - NQ));
        uint2 o; o.x = pkbf(v.x, v.y); o.y = pkbf(v.z, v.w);
        *(uint2*)(g_wo + (i4 - NQ)) = o;
    }
}

// ======================= 0b) mask compaction (deterministic scan) ==========
// One block per batch; order-preserving -> deterministic output and
// summation order (subsequence of the uncompacted order).
__global__ void __launch_bounds__(1024) compact_kernel(const int* __restrict__ mask)
{
    __shared__ int sc[1024];
    int b = blockIdx.x, t = threadIdx.x;
    int m0 = (mask[b*SS + 2*t]     == 0) ? 1 : 0;
    int m1 = (mask[b*SS + 2*t + 1] == 0) ? 1 : 0;
    sc[t] = m0 + m1;
    __syncthreads();
    #pragma unroll
    for (int off = 1; off < 1024; off <<= 1) {
        int v = (t >= off) ? sc[t - off] : 0;
        __syncthreads();
        sc[t] += v;
        __syncthreads();
    }
    int excl = sc[t] - m0 - m1;
    if (m0) g_idx[b*SS + excl]      = 2*t;
    if (m1) g_idx[b*SS + excl + m0] = 2*t + 1;
    if (t == 1023) g_cnt[b] = sc[1023];
}

// ======================= 1) LayerNorm (f32 in -> bf16 out) =================
__global__ void __launch_bounds__(256) ln_kernel(
    const float* __restrict__ x,
    const float* __restrict__ gamma,
    const float* __restrict__ beta)
{
    int row = blockIdx.x;
    int tid = threadIdx.x;
    const float4 xv = *(const float4*)&x[row*HH + tid*4];

    float s  = xv.x + xv.y + xv.z + xv.w;
    float s2 = xv.x*xv.x + xv.y*xv.y + xv.z*xv.z + xv.w*xv.w;
    #pragma unroll
    for (int o = 16; o > 0; o >>= 1) {
        s  += __shfl_down_sync(0xffffffffu, s,  o);
        s2 += __shfl_down_sync(0xffffffffu, s2, o);
    }
    __shared__ float ss[8], ss2[8];
    if ((tid & 31) == 0) { ss[tid >> 5] = s; ss2[tid >> 5] = s2; }
    __syncthreads();
    float ts = 0.f, ts2 = 0.f;
    #pragma unroll
    for (int w = 0; w < 8; w++) { ts += ss[w]; ts2 += ss2[w]; }

    float mu   = ts * (1.0f / HH);
    float var  = ts2 * (1.0f / HH) - mu * mu;
    float rstd = rsqrtf(var + 1e-5f);

    const float4 gv = *(const float4*)&gamma[tid*4];
    const float4 bv = *(const float4*)&beta[tid*4];
    uint2 o2;
    o2.x = pkbf((xv.x - mu)*rstd*gv.x + bv.x, (xv.y - mu)*rstd*gv.y + bv.y);
    o2.y = pkbf((xv.z - mu)*rstd*gv.z + bv.z, (xv.w - mu)*rstd*gv.w + bv.w);
    *(uint2*)&g_y[row*HH + tid*4] = o2;
}

// ======================= bf16 GEMM (128x128, 8 warps, 64x32 warp tile) =====
// 3-stage cp.async pipeline, k-step 32; both operands bf16 in gmem.
#define GST      40               // halves; 80B = odd multiple of 16B
#define STAGE_H  (128*GST)        // 5120 halves per operand per stage
#define GSMEM_H  (2*STAGE_H)      // A+B per stage
#define GEMM_SMEM (3*GSMEM_H*2)   // 61440 B

#define GEMM_PREFETCH(kt) do {                                              \
    int s_ = (kt) % 3;                                                      \
    int r_ = tid >> 1;                                                      \
    int h_ = (tid & 1) * 16;                                                \
    unsigned aDst = dsmB + (unsigned)((s_*GSMEM_H + r_*GST + h_) * 2);      \
    unsigned bDst = aDst + STAGE_H*2;                                       \
    const __nv_bfloat16* a_ = Ag + (size_t)r_*HH + (kt)*32 + h_;            \
    const __nv_bfloat16* b_ = Bg + (size_t)r_*HH + (kt)*32 + h_;            \
    cpa16(aDst,      a_);                                                   \
    cpa16(aDst + 16, a_ + 8);                                               \
    cpa16(bDst,      b_);                                                   \
    cpa16(bDst + 16, b_ + 8);                                               \
} while (0)

#define GEMM_MAINLOOP(ACC)                                                  \
    GEMM_PREFETCH(0); cpa_commit();                                         \
    GEMM_PREFETCH(1); cpa_commit();                                         \
    const unsigned aOff = (unsigned)(((warp_m + (lane & 15))*GST + (lane >> 4)*8) * 2);            \
    const unsigned bOff = (unsigned)(((warp_n + (lane >> 4)*8 + (lane & 7))*GST + ((lane >> 3) & 1)*8) * 2) + STAGE_H*2; \
    for (int kt = 0; kt < 32; kt++) {                                       \
        cpa_wait<1>();                                                      \
        __syncthreads();                                                    \
        if (kt + 2 < 32) { GEMM_PREFETCH(kt + 2); }                         \
        cpa_commit();                                                       \
        unsigned sB = dsmB + (unsigned)((kt % 3)*GSMEM_H*2);                \
        _Pragma("unroll")                                                   \
        for (int kc = 0; kc < 2; kc++) {                                    \
            unsigned af[4][4], bf[2][4];                                    \
            _Pragma("unroll")                                               \
            for (int mt = 0; mt < 4; mt++)                                  \
                ldsm_x4(af[mt], sB + aOff + (unsigned)((mt*16*GST + kc*16)*2)); \
            _Pragma("unroll")                                               \
            for (int np = 0; np < 2; np++)                                  \
                ldsm_x4(bf[np], sB + bOff + (unsigned)((np*16*GST + kc*16)*2)); \
            _Pragma("unroll")                                               \
            for (int mt = 0; mt < 4; mt++)                                  \
                _Pragma("unroll")                                           \
                for (int np = 0; np < 2; np++) {                            \
                    mma_bf16(ACC[mt][2*np],   af[mt], &bf[np][0]);          \
                    mma_bf16(ACC[mt][2*np+1], af[mt], &bf[np][2]);          \
                }                                                           \
        }                                                                   \
    }

// ---- QKV GEMM: epilogue scatters bf16 to g_q/g_k/g_v [b,h,s,d] ------------
__global__ void __launch_bounds__(256, 2) gemm_qkv_kernel(const float* __restrict__ bias)
{
    extern __shared__ __nv_bfloat16 dsm[];
    const int tid = threadIdx.x, lane = tid & 31, w = tid >> 5;
    const int warp_m = (w >> 2) * 64, warp_n = (w & 3) * 32;
    const int n0 = blockIdx.x * 128, m0 = blockIdx.y * 128;
    const __nv_bfloat16* Ag = g_y  + (size_t)m0 * HH;
    const __nv_bfloat16* Bg = g_wq + (size_t)n0 * HH;
    const unsigned dsmB = (unsigned)__cvta_generic_to_shared(dsm);

    float acc[4][4][4] = {};
    GEMM_MAINLOOP(acc)

    const int g = lane >> 2, t2 = (lane & 3) * 2;
    #pragma unroll
    for (int nt = 0; nt < 4; nt++) {
        int gn = n0 + warp_n + nt*8 + t2;
        int grp = gn >> 10, head = (gn >> 6) & 15, d = gn & 63;
        __nv_bfloat16* dst = (grp == 0) ? g_q : (grp == 1) ? g_k : g_v;
        float2 bi = *(const float2*)&bias[gn];
        #pragma unroll
        for (int mt = 0; mt < 4; mt++) {
            int m = m0 + warp_m + mt*16 + g;
            int b = m >> 11, s = m & 2047;
            __nv_bfloat16* p = &dst[((size_t)(b*NH + head)*SS + s)*HD + d];
            *(unsigned*)p          = pkbf(acc[mt][nt][0] + bi.x, acc[mt][nt][1] + bi.y);
            *(unsigned*)(p + 8*HD) = pkbf(acc[mt][nt][2] + bi.x, acc[mt][nt][3] + bi.y);
        }
    }
}

// ---- Output GEMM: + bias + residual (f32 out) -----------------------------
__global__ void __launch_bounds__(256, 2) gemm_out_kernel(
    const float* __restrict__ bias,
    const float* __restrict__ x,
    float* __restrict__ out)
{
    extern __shared__ __nv_bfloat16 dsm[];
    const int tid = threadIdx.x, lane = tid & 31, w = tid >> 5;
    const int warp_m = (w >> 2) * 64, warp_n = (w & 3) * 32;
    const int n0 = blockIdx.x * 128, m0 = blockIdx.y * 128;
    const __nv_bfloat16* Ag = g_ctx + (size_t)m0 * HH;
    const __nv_bfloat16* Bg = g_wo  + (size_t)n0 * HH;
    const unsigned dsmB = (unsigned)__cvta_generic_to_shared(dsm);

    float acc[4][4][4] = {};
    GEMM_MAINLOOP(acc)

    const int g = lane >> 2, t2 = (lane & 3) * 2;
    #pragma unroll
    for (int nt = 0; nt < 4; nt++) {
        int gn = n0 + warp_n + nt*8 + t2;
        float2 bi = *(const float2*)&bias[gn];
        #pragma unroll
        for (int mt = 0; mt < 4; mt++) {
            int m = m0 + warp_m + mt*16 + g;
            const float2 x0 = *(const float2*)&x[(size_t)m*HH + gn];
            const float2 x1 = *(const float2*)&x[(size_t)(m+8)*HH + gn];
            float2 v0 = {acc[mt][nt][0] + bi.x + x0.x, acc[mt][nt][1] + bi.y + x0.y};
            float2 v1 = {acc[mt][nt][2] + bi.x + x1.x, acc[mt][nt][3] + bi.y + x1.y};
            *(float2*)&out[(size_t)m*HH + gn]     = v0;
            *(float2*)&out[(size_t)(m+8)*HH + gn] = v1;
        }
    }
}

// ======================= 3) Flash attention over COMPACTED keys ============
// 256 threads (8 warps); q-tile 128 (16 rows/warp), k-tile 64.
// Only unmasked keys (per-batch compacted index list) are attended; masked
// keys contribute exactly 0 to numerator and denominator (f32 underflow in
// the reference), so dropping them is exact. Padding lanes in the last tile
// get bias -1e30 -> p = 0. Valid keys need no mask bias at all.
#define AST 72
#define ATT_KV_H   (64*AST)
#define ATT_K_OFF  (128*AST)
#define ATT_V_OFF  (128*AST + 2*ATT_KV_H)
#define ATT_SMEM   ((128*AST + 4*ATT_KV_H)*2)   // 55296 B
#define LOG2E 1.44269504f

#define ATT_PREFETCH(it) do {                                               \
    int s_ = (it) & 1;                                                      \
    int r_ = tid >> 2;                                                      \
    int ch_ = (tid & 3) * 2;                                                \
    int j_ = (it)*64 + r_;                                                  \
    int row_ = (j_ < ncnt) ? idxb[j_] : 0;                                  \
    unsigned kDst = base + (unsigned)((ATT_K_OFF + s_*ATT_KV_H + r_*AST)*2); \
    unsigned vDst = base + (unsigned)((ATT_V_OFF + s_*ATT_KV_H + r_*AST)*2); \
    const __nv_bfloat16* kp = Kg + (size_t)row_*HD;                         \
    const __nv_bfloat16* vp = Vg + (size_t)row_*HD;                         \
    _Pragma("unroll")                                                       \
    for (int c_ = 0; c_ < 2; c_++) {                                        \
        cpa16(kDst + (ch_ + c_)*16, kp + (ch_ + c_)*8);                     \
        cpa16(vDst + (ch_ + c_)*16, vp + (ch_ + c_)*8);                     \
    }                                                                       \
    if (tid < 64) ms2[s_][tid] = ((it)*64 + tid < ncnt) ? 0.f : -1e30f;     \
} while (0)

__global__ void __launch_bounds__(256, 2) attn_kernel(void)
{
    extern __shared__ __nv_bfloat16 smp[];
    __shared__ float ms2[2][64];

    const int tid  = threadIdx.x;
    const int lane = tid & 31;
    const int w    = tid >> 5;
    const int bh = blockIdx.y;
    const int q0 = blockIdx.x * 128;
    const int b  = bh >> 4, h = bh & 15;

    const __nv_bfloat16* Qg = g_q + (size_t)bh * SS * HD;
    const __nv_bfloat16* Kg = g_k + (size_t)bh * SS * HD;
    const __nv_bfloat16* Vg = g_v + (size_t)bh * SS * HD;
    const int* idxb = g_idx + b * SS;
    const int  ncnt = g_cnt[b];
    const int  nt_total = (ncnt + 63) >> 6;

    const unsigned base = (unsigned)__cvta_generic_to_shared(smp);

    // stage Q (bf16 copy) + prefetch K/V tile 0
    {
        int r = tid >> 1, c0 = (tid & 1) * 32;
        #pragma unroll
        for (int i = 0; i < 4; i++)
            *(uint4*)&smp[r*AST + c0 + i*8] =
                *(const uint4*)&Qg[(size_t)(q0 + r)*HD + c0 + i*8];
    }
    ATT_PREFETCH(0);
    cpa_commit();
    __syncthreads();

    // cache Q fragments (4 d-chunks)
    const unsigned qBase = base + (unsigned)(((w*16 + (lane & 15))*AST + (lane >> 4)*8) * 2);
    unsigned qf[4][4];
    #pragma unroll
    for (int dc = 0; dc < 4; dc++)
        ldsm_x4(qf[dc], qBase + (unsigned)(dc*16*2));

    const unsigned kOff = (unsigned)((((lane >> 4)*8 + (lane & 7))*AST + ((lane >> 3) & 1)*8) * 2);
    const unsigned vOff = (unsigned)(((((lane >> 3) & 1)*8 + (lane & 7))*AST + (lane >> 4)*8) * 2);

    float o[8][4] = {};
    float lrun0 = 0.f, lrun1 = 0.f;
    const int t2 = (lane & 3) * 2;
    const float SC2 = 0.125f * LOG2E;

    for (int it = 0; it < nt_total; it++) {
        if (it + 1 < nt_total) { ATT_PREFETCH(it + 1); }
        cpa_commit();
        cpa_wait<1>();
        __syncthreads();

        const unsigned kS = base + (unsigned)((ATT_K_OFF + (it & 1)*ATT_KV_H)*2);
        const unsigned vS = base + (unsigned)((ATT_V_OFF + (it & 1)*ATT_KV_H)*2);
        const float* msp = ms2[it & 1];

        // S = Q K^T (64 compacted keys)
        float ss[8][4] = {};
        #pragma unroll
        for (int dc = 0; dc < 4; dc++) {
            #pragma unroll
            for (int np = 0; np < 4; np++) {
                unsigned bk[4];
                ldsm_x4(bk, kS + kOff + (unsigned)((np*16*AST + dc*16) * 2));
                mma_bf16(ss[2*np],   qf[dc], &bk[0]);
                mma_bf16(ss[2*np+1], qf[dc], &bk[2]);
            }
        }

        // p = 2^(s*SC2 + bias); bias 0 for valid keys, -1e30 for padding
        #pragma unroll
        for (int nt = 0; nt < 8; nt++) {
            float b0 = msp[nt*8 + t2], b1 = msp[nt*8 + t2 + 1];
            ss[nt][0] = ex2(ss[nt][0]*SC2 + b0);
            ss[nt][1] = ex2(ss[nt][1]*SC2 + b1);
            ss[nt][2] = ex2(ss[nt][2]*SC2 + b0);
            ss[nt][3] = ex2(ss[nt][3]*SC2 + b1);
            lrun0 += ss[nt][0] + ss[nt][1];
            lrun1 += ss[nt][2] + ss[nt][3];
        }

        // O += P V
        #pragma unroll
        for (int kc = 0; kc < 4; kc++) {
            unsigned ap[4];
            ap[0] = pkbf(ss[2*kc][0],   ss[2*kc][1]);
            ap[1] = pkbf(ss[2*kc][2],   ss[2*kc][3]);
            ap[2] = pkbf(ss[2*kc+1][0], ss[2*kc+1][1]);
            ap[3] = pkbf(ss[2*kc+1][2], ss[2*kc+1][3]);
            #pragma unroll
            for (int p = 0; p < 4; p++) {
                unsigned bv[4];
                ldsm_x4t(bv, vS + vOff + (unsigned)((kc*16*AST + p*16) * 2));
                mma_bf16(o[2*p],   ap, &bv[0]);
                mma_bf16(o[2*p+1], ap, &bv[2]);
            }
        }
        __syncthreads();   // stage (it&1) free for prefetch at it+1
    }

    // epilogue: single cross-lane sum reduction, then normalize + store
    lrun0 += __shfl_xor_sync(0xffffffffu, lrun0, 1);
    lrun0 += __shfl_xor_sync(0xffffffffu, lrun0, 2);
    lrun1 += __shfl_xor_sync(0xffffffffu, lrun1, 1);
    lrun1 += __shfl_xor_sync(0xffffffffu, lrun1, 2);
    float inv0 = 1.0f / lrun0, inv1 = 1.0f / lrun1;
    int r0 = q0 + w*16 + (lane >> 2);
    #pragma unroll
    for (int dt = 0; dt < 8; dt++) {
        int d = dt*8 + t2;
        *(unsigned*)&g_ctx[((size_t)b*SS + r0)*HH + h*HD + d] =
            pkbf(o[dt][0]*inv0, o[dt][1]*inv0);
        *(unsigned*)&g_ctx[((size_t)b*SS + r0 + 8)*HH + h*HD + d] =
            pkbf(o[dt][2]*inv1, o[dt][3]*inv1);
    }
}

// ======================= launch ============================================
extern "C" void kernel_launch(void* const* d_in, const int* in_sizes, int n_in,
                              void* d_out, int out_size)
{
    const float* x      = (const float*)d_in[0];
    const int*   mask   = (const int*)  d_in[1];
    const float* qkv_w  = (const float*)d_in[2];
    const float* qkv_b  = (const float*)d_in[3];
    const float* out_w  = (const float*)d_in[4];
    const float* out_b  = (const float*)d_in[5];
    const float* gamma  = (const float*)d_in[6];
    const float* beta   = (const float*)d_in[7];
    float* out = (float*)d_out;

    cudaFuncSetAttribute(gemm_qkv_kernel,
                         cudaFuncAttributeMaxDynamicSharedMemorySize, GEMM_SMEM);
    cudaFuncSetAttribute(gemm_out_kernel,
                         cudaFuncAttributeMaxDynamicSharedMemorySize, GEMM_SMEM);
    cudaFuncSetAttribute(attn_kernel,
                         cudaFuncAttributeMaxDynamicSharedMemorySize, ATT_SMEM);

    // 0) weights -> bf16; mask compaction
    wcvt_kernel<<<4096, 256>>>(qkv_w, out_w);
    compact_kernel<<<BB, 1024>>>(mask);

    // 1) LayerNorm (f32 -> bf16)
    ln_kernel<<<MM, 256>>>(x, gamma, beta);

    // 2) QKV projection: N=3072, M=8192
    gemm_qkv_kernel<<<dim3(3*HH/128, MM/128), 256, GEMM_SMEM>>>(qkv_b);

    // 3) attention over compacted keys: 16 q-tiles x 64 (b,h)
    attn_kernel<<<dim3(SS/128, BB*NH), 256, ATT_SMEM>>>();

    // 4) output projection + bias + residual
    gemm_out_kernel<<<dim3(HH/128, MM/128), 256, GEMM_SMEM>>>(out_b, x, out);
}

// round 15
// speedup vs baseline: 1.4329x; 1.1269x over previous
#include <cuda_runtime.h>
#include <cuda_bf16.h>
#include <math.h>

#define BB 4
#define SS 2048
#define HH 1024
#define NH 16
#define HD 64
#define MM (BB*SS)          // 8192 rows

// ---------------- scratch (device globals; no allocation allowed) ----------
__device__ __nv_bfloat16 g_y[BB*SS*HH];        // LN output        16 MB
__device__ __nv_bfloat16 g_q[BB*NH*SS*HD];     // Q [b,h,s,d]      16 MB
__device__ __nv_bfloat16 g_k[BB*NH*SS*HD];     // K [b,h,j,d] compacted
__device__ __nv_bfloat16 g_v[BB*NH*SS*HD];     // V [b,h,j,d] compacted
__device__ __nv_bfloat16 g_ctx[BB*SS*HH];      // attention ctx    16 MB
__device__ __nv_bfloat16 g_wq[3*HH*HH];        // bf16 qkv weights  6 MB
__device__ __nv_bfloat16 g_wo[HH*HH];          // bf16 out weights  2 MB
__device__ int g_idx[BB*SS];                   // compacted unmasked key idx
__device__ int g_cnt[BB];                      // unmasked count per batch

// ---------------- helpers ---------------------------------------------------
__device__ __forceinline__ unsigned pkbf(float lo, float hi) {
    __nv_bfloat162 h = __float22bfloat162_rn(make_float2(lo, hi));
    return *(unsigned*)&h;
}
__device__ __forceinline__ void mma_bf16(float* d, const unsigned* a, const unsigned* b) {
    asm("mma.sync.aligned.m16n8k16.row.col.f32.bf16.bf16.f32 "
        "{%0,%1,%2,%3},{%4,%5,%6,%7},{%8,%9},{%0,%1,%2,%3};"
        : "+f"(d[0]), "+f"(d[1]), "+f"(d[2]), "+f"(d[3])
        : "r"(a[0]), "r"(a[1]), "r"(a[2]), "r"(a[3]), "r"(b[0]), "r"(b[1]));
}
__device__ __forceinline__ void ldsm_x4(unsigned* r, unsigned addr) {
    asm volatile("ldmatrix.sync.aligned.m8n8.x4.shared.b16 {%0,%1,%2,%3},[%4];"
        : "=r"(r[0]), "=r"(r[1]), "=r"(r[2]), "=r"(r[3]) : "r"(addr));
}
__device__ __forceinline__ void ldsm_x4t(unsigned* r, unsigned addr) {
    asm volatile("ldmatrix.sync.aligned.m8n8.x4.trans.shared.b16 {%0,%1,%2,%3},[%4];"
        : "=r"(r[0]), "=r"(r[1]), "=r"(r[2]), "=r"(r[3]) : "r"(addr));
}
__device__ __forceinline__ void cpa16(unsigned dst, const void* src) {
    asm volatile("cp.async.cg.shared.global [%0], [%1], 16;" :: "r"(dst), "l"(src));
}
__device__ __forceinline__ void cpa_commit() {
    asm volatile("cp.async.commit_group;" ::: "memory");
}
template<int N> __device__ __forceinline__ void cpa_wait() {
    asm volatile("cp.async.wait_group %0;" :: "n"(N) : "memory");
}
__device__ __forceinline__ float ex2(float x) {
    float r; asm("ex2.approx.f32 %0, %1;" : "=f"(r) : "f"(x)); return r;
}

// ======================= 0) weight convert (f32 -> bf16) ===================
__global__ void __launch_bounds__(256) wcvt_kernel(
    const float* __restrict__ qw, const float* __restrict__ ow)
{
    const int NQ = 3*HH*HH;
    int i4 = (blockIdx.x*256 + threadIdx.x) * 4;
    if (i4 < NQ) {
        float4 v = *(const float4*)(qw + i4);
        uint2 o; o.x = pkbf(v.x, v.y); o.y = pkbf(v.z, v.w);
        *(uint2*)(g_wq + i4) = o;
    } else {
        float4 v = *(const float4*)(ow + (i4 - NQ));
        uint2 o; o.x = pkbf(v.x, v.y); o.y = pkbf(v.z, v.w);
        *(uint2*)(g_wo + (i4 - NQ)) = o;
    }
}

// ======================= 0b) mask compaction (deterministic scan) ==========
__global__ void __launch_bounds__(1024) compact_kernel(const int* __restrict__ mask)
{
    __shared__ int sc[1024];
    int b = blockIdx.x, t = threadIdx.x;
    int m0 = (mask[b*SS + 2*t]     == 0) ? 1 : 0;
    int m1 = (mask[b*SS + 2*t + 1] == 0) ? 1 : 0;
    sc[t] = m0 + m1;
    __syncthreads();
    #pragma unroll
    for (int off = 1; off < 1024; off <<= 1) {
        int v = (t >= off) ? sc[t - off] : 0;
        __syncthreads();
        sc[t] += v;
        __syncthreads();
    }
    int excl = sc[t] - m0 - m1;
    if (m0) g_idx[b*SS + excl]      = 2*t;
    if (m1) g_idx[b*SS + excl + m0] = 2*t + 1;
    if (t == 1023) g_cnt[b] = sc[1023];
}

// ======================= 1) LayerNorm (f32 in -> bf16 out) =================
__global__ void __launch_bounds__(256) ln_kernel(
    const float* __restrict__ x,
    const float* __restrict__ gamma,
    const float* __restrict__ beta)
{
    int row = blockIdx.x;
    int tid = threadIdx.x;
    const float4 xv = *(const float4*)&x[row*HH + tid*4];

    float s  = xv.x + xv.y + xv.z + xv.w;
    float s2 = xv.x*xv.x + xv.y*xv.y + xv.z*xv.z + xv.w*xv.w;
    #pragma unroll
    for (int o = 16; o > 0; o >>= 1) {
        s  += __shfl_down_sync(0xffffffffu, s,  o);
        s2 += __shfl_down_sync(0xffffffffu, s2, o);
    }
    __shared__ float ss[8], ss2[8];
    if ((tid & 31) == 0) { ss[tid >> 5] = s; ss2[tid >> 5] = s2; }
    __syncthreads();
    float ts = 0.f, ts2 = 0.f;
    #pragma unroll
    for (int w = 0; w < 8; w++) { ts += ss[w]; ts2 += ss2[w]; }

    float mu   = ts * (1.0f / HH);
    float var  = ts2 * (1.0f / HH) - mu * mu;
    float rstd = rsqrtf(var + 1e-5f);

    const float4 gv = *(const float4*)&gamma[tid*4];
    const float4 bv = *(const float4*)&beta[tid*4];
    uint2 o2;
    o2.x = pkbf((xv.x - mu)*rstd*gv.x + bv.x, (xv.y - mu)*rstd*gv.y + bv.y);
    o2.y = pkbf((xv.z - mu)*rstd*gv.z + bv.z, (xv.w - mu)*rstd*gv.w + bv.w);
    *(uint2*)&g_y[row*HH + tid*4] = o2;
}

// ======================= bf16 GEMM (128x128, 8 warps, 64x32 warp tile) =====
// 3-stage cp.async pipeline, k-step 32.  Per-thread row pointers Agp/Bgp are
// hoisted out of the k-loop (thread owns staging row tid>>1 for the run).
#define GST      40               // halves; 80B = odd multiple of 16B
#define STAGE_H  (128*GST)        // 5120 halves per operand per stage
#define GSMEM_H  (2*STAGE_H)      // A+B per stage
#define GEMM_SMEM (3*GSMEM_H*2)   // 61440 B

#define GEMM_PREFETCH(kt) do {                                              \
    int s_ = (kt) % 3;                                                      \
    int r_ = tid >> 1;                                                      \
    int h_ = (tid & 1) * 16;                                                \
    unsigned aDst = dsmB + (unsigned)((s_*GSMEM_H + r_*GST + h_) * 2);      \
    unsigned bDst = aDst + STAGE_H*2;                                       \
    const __nv_bfloat16* a_ = Agp + (kt)*32 + h_;                           \
    const __nv_bfloat16* b_ = Bgp + (kt)*32 + h_;                           \
    cpa16(aDst,      a_);                                                   \
    cpa16(aDst + 16, a_ + 8);                                               \
    cpa16(bDst,      b_);                                                   \
    cpa16(bDst + 16, b_ + 8);                                               \
} while (0)

#define GEMM_MAINLOOP(ACC)                                                  \
    GEMM_PREFETCH(0); cpa_commit();                                         \
    GEMM_PREFETCH(1); cpa_commit();                                         \
    const unsigned aOff = (unsigned)(((warp_m + (lane & 15))*GST + (lane >> 4)*8) * 2);            \
    const unsigned bOff = (unsigned)(((warp_n + (lane >> 4)*8 + (lane & 7))*GST + ((lane >> 3) & 1)*8) * 2) + STAGE_H*2; \
    for (int kt = 0; kt < 32; kt++) {                                       \
        cpa_wait<1>();                                                      \
        __syncthreads();                                                    \
        if (kt + 2 < 32) { GEMM_PREFETCH(kt + 2); }                         \
        cpa_commit();                                                       \
        unsigned sB = dsmB + (unsigned)((kt % 3)*GSMEM_H*2);                \
        _Pragma("unroll")                                                   \
        for (int kc = 0; kc < 2; kc++) {                                    \
            unsigned af[4][4], bf[2][4];                                    \
            _Pragma("unroll")                                               \
            for (int mt = 0; mt < 4; mt++)                                  \
                ldsm_x4(af[mt], sB + aOff + (unsigned)((mt*16*GST + kc*16)*2)); \
            _Pragma("unroll")                                               \
            for (int np = 0; np < 2; np++)                                  \
                ldsm_x4(bf[np], sB + bOff + (unsigned)((np*16*GST + kc*16)*2)); \
            _Pragma("unroll")                                               \
            for (int mt = 0; mt < 4; mt++)                                  \
                _Pragma("unroll")                                           \
                for (int np = 0; np < 2; np++) {                            \
                    mma_bf16(ACC[mt][2*np],   af[mt], &bf[np][0]);          \
                    mma_bf16(ACC[mt][2*np+1], af[mt], &bf[np][2]);          \
                }                                                           \
        }                                                                   \
    }

// ---- Q GEMM: N=1024, all rows; scatters bf16 to g_q [b,h,s,d] -------------
__global__ void __launch_bounds__(256, 2) gemm_q_kernel(const float* __restrict__ bias)
{
    extern __shared__ __nv_bfloat16 dsm[];
    const int tid = threadIdx.x, lane = tid & 31, w = tid >> 5;
    const int warp_m = (w >> 2) * 64, warp_n = (w & 3) * 32;
    const int n0 = blockIdx.x * 128, m0 = blockIdx.y * 128;
    const __nv_bfloat16* Agp = g_y  + (size_t)(m0 + (tid >> 1)) * HH;
    const __nv_bfloat16* Bgp = g_wq + (size_t)(n0 + (tid >> 1)) * HH;
    const unsigned dsmB = (unsigned)__cvta_generic_to_shared(dsm);

    float acc[4][4][4] = {};
    GEMM_MAINLOOP(acc)

    const int g = lane >> 2, t2 = (lane & 3) * 2;
    #pragma unroll
    for (int nt = 0; nt < 4; nt++) {
        int gn = n0 + warp_n + nt*8 + t2;
        int head = (gn >> 6) & 15, d = gn & 63;
        float2 bi = *(const float2*)&bias[gn];
        #pragma unroll
        for (int mt = 0; mt < 4; mt++) {
            int m = m0 + warp_m + mt*16 + g;
            int b = m >> 11, s = m & 2047;
            __nv_bfloat16* p = &g_q[((size_t)(b*NH + head)*SS + s)*HD + d];
            *(unsigned*)p          = pkbf(acc[mt][nt][0] + bi.x, acc[mt][nt][1] + bi.y);
            *(unsigned*)(p + 8*HD) = pkbf(acc[mt][nt][2] + bi.x, acc[mt][nt][3] + bi.y);
        }
    }
}

// ---- KV GEMM: N=2048, only compacted rows; writes compacted g_k/g_v -------
// grid.y = b*16 + m-tile; early-exit when tile beyond g_cnt[b].
__global__ void __launch_bounds__(256, 2) gemm_kv_kernel(const float* __restrict__ bias)
{
    extern __shared__ __nv_bfloat16 dsm[];
    const int tid = threadIdx.x, lane = tid & 31, w = tid >> 5;
    const int warp_m = (w >> 2) * 64, warp_n = (w & 3) * 32;
    const int n0 = blockIdx.x * 128;
    const int b  = blockIdx.y >> 4;
    const int m0 = (blockIdx.y & 15) * 128;
    const int cnt = g_cnt[b];
    if (m0 >= cnt) return;

    const int* idxb = g_idx + b * SS;
    int j = m0 + (tid >> 1);
    int srow = idxb[(j < cnt) ? j : 0];
    const __nv_bfloat16* Agp = g_y  + (size_t)(b*SS + srow) * HH;
    const __nv_bfloat16* Bgp = g_wq + (size_t)(HH + n0 + (tid >> 1)) * HH;
    const unsigned dsmB = (unsigned)__cvta_generic_to_shared(dsm);

    float acc[4][4][4] = {};
    GEMM_MAINLOOP(acc)

    const int g = lane >> 2, t2 = (lane & 3) * 2;
    #pragma unroll
    for (int nt = 0; nt < 4; nt++) {
        int gn = n0 + warp_n + nt*8 + t2;          // 0..2047: K then V
        int grp = gn >> 10, head = (gn >> 6) & 15, d = gn & 63;
        __nv_bfloat16* dst = (grp == 0) ? g_k : g_v;
        float2 bi = *(const float2*)&bias[HH + gn];
        #pragma unroll
        for (int mt = 0; mt < 4; mt++) {
            int jj = m0 + warp_m + mt*16 + g;      // compacted slot
            __nv_bfloat16* p = &dst[((size_t)(b*NH + head)*SS + jj)*HD + d];
            *(unsigned*)p          = pkbf(acc[mt][nt][0] + bi.x, acc[mt][nt][1] + bi.y);
            *(unsigned*)(p + 8*HD) = pkbf(acc[mt][nt][2] + bi.x, acc[mt][nt][3] + bi.y);
        }
    }
}

// ---- Output GEMM: + bias + residual (f32 out) -----------------------------
__global__ void __launch_bounds__(256, 2) gemm_out_kernel(
    const float* __restrict__ bias,
    const float* __restrict__ x,
    float* __restrict__ out)
{
    extern __shared__ __nv_bfloat16 dsm[];
    const int tid = threadIdx.x, lane = tid & 31, w = tid >> 5;
    const int warp_m = (w >> 2) * 64, warp_n = (w & 3) * 32;
    const int n0 = blockIdx.x * 128, m0 = blockIdx.y * 128;
    const __nv_bfloat16* Agp = g_ctx + (size_t)(m0 + (tid >> 1)) * HH;
    const __nv_bfloat16* Bgp = g_wo  + (size_t)(n0 + (tid >> 1)) * HH;
    const unsigned dsmB = (unsigned)__cvta_generic_to_shared(dsm);

    float acc[4][4][4] = {};
    GEMM_MAINLOOP(acc)

    const int g = lane >> 2, t2 = (lane & 3) * 2;
    #pragma unroll
    for (int nt = 0; nt < 4; nt++) {
        int gn = n0 + warp_n + nt*8 + t2;
        float2 bi = *(const float2*)&bias[gn];
        #pragma unroll
        for (int mt = 0; mt < 4; mt++) {
            int m = m0 + warp_m + mt*16 + g;
            const float2 x0 = *(const float2*)&x[(size_t)m*HH + gn];
            const float2 x1 = *(const float2*)&x[(size_t)(m+8)*HH + gn];
            float2 v0 = {acc[mt][nt][0] + bi.x + x0.x, acc[mt][nt][1] + bi.y + x0.y};
            float2 v1 = {acc[mt][nt][2] + bi.x + x1.x, acc[mt][nt][3] + bi.y + x1.y};
            *(float2*)&out[(size_t)m*HH + gn]     = v0;
            *(float2*)&out[(size_t)(m+8)*HH + gn] = v1;
        }
    }
}

// ======================= 3) Flash attention over COMPACTED K/V =============
// K/V already stored compacted per (b,h) -> sequential prefetch, no gather.
// Padding lanes in the last tile get bias -1e30 -> p = 0.
#define AST 72
#define ATT_KV_H   (64*AST)
#define ATT_K_OFF  (128*AST)
#define ATT_V_OFF  (128*AST + 2*ATT_KV_H)
#define ATT_SMEM   ((128*AST + 4*ATT_KV_H)*2)   // 55296 B
#define LOG2E 1.44269504f

#define ATT_PREFETCH(it) do {                                               \
    int s_ = (it) & 1;                                                      \
    int r_ = tid >> 2;                                                      \
    int ch_ = (tid & 3) * 2;                                                \
    unsigned kDst = base + (unsigned)((ATT_K_OFF + s_*ATT_KV_H + r_*AST)*2); \
    unsigned vDst = base + (unsigned)((ATT_V_OFF + s_*ATT_KV_H + r_*AST)*2); \
    const __nv_bfloat16* kp = Kg + (size_t)((it)*64 + r_)*HD;               \
    const __nv_bfloat16* vp = Vg + (size_t)((it)*64 + r_)*HD;               \
    _Pragma("unroll")                                                       \
    for (int c_ = 0; c_ < 2; c_++) {                                        \
        cpa16(kDst + (ch_ + c_)*16, kp + (ch_ + c_)*8);                     \
        cpa16(vDst + (ch_ + c_)*16, vp + (ch_ + c_)*8);                     \
    }                                                                       \
    if (tid < 64) ms2[s_][tid] = ((it)*64 + tid < ncnt) ? 0.f : -1e30f;     \
} while (0)

__global__ void __launch_bounds__(256, 2) attn_kernel(void)
{
    extern __shared__ __nv_bfloat16 smp[];
    __shared__ float ms2[2][64];

    const int tid  = threadIdx.x;
    const int lane = tid & 31;
    const int w    = tid >> 5;
    const int bh = blockIdx.y;
    const int q0 = blockIdx.x * 128;
    const int b  = bh >> 4, h = bh & 15;

    const __nv_bfloat16* Qg = g_q + (size_t)bh * SS * HD;
    const __nv_bfloat16* Kg = g_k + (size_t)bh * SS * HD;
    const __nv_bfloat16* Vg = g_v + (size_t)bh * SS * HD;
    const int  ncnt = g_cnt[b];
    const int  nt_total = (ncnt + 63) >> 6;

    const unsigned base = (unsigned)__cvta_generic_to_shared(smp);

    // stage Q (bf16 copy) + prefetch K/V tile 0
    {
        int r = tid >> 1, c0 = (tid & 1) * 32;
        #pragma unroll
        for (int i = 0; i < 4; i++)
            *(uint4*)&smp[r*AST + c0 + i*8] =
                *(const uint4*)&Qg[(size_t)(q0 + r)*HD + c0 + i*8];
    }
    ATT_PREFETCH(0);
    cpa_commit();
    __syncthreads();

    // cache Q fragments (4 d-chunks)
    const unsigned qBase = base + (unsigned)(((w*16 + (lane & 15))*AST + (lane >> 4)*8) * 2);
    unsigned qf[4][4];
    #pragma unroll
    for (int dc = 0; dc < 4; dc++)
        ldsm_x4(qf[dc], qBase + (unsigned)(dc*16*2));

    const unsigned kOff = (unsigned)((((lane >> 4)*8 + (lane & 7))*AST + ((lane >> 3) & 1)*8) * 2);
    const unsigned vOff = (unsigned)(((((lane >> 3) & 1)*8 + (lane & 7))*AST + (lane >> 4)*8) * 2);

    float o[8][4] = {};
    float lrun0 = 0.f, lrun1 = 0.f;
    const int t2 = (lane & 3) * 2;
    const float SC2 = 0.125f * LOG2E;

    for (int it = 0; it < nt_total; it++) {
        if (it + 1 < nt_total) { ATT_PREFETCH(it + 1); }
        cpa_commit();
        cpa_wait<1>();
        __syncthreads();

        const unsigned kS = base + (unsigned)((ATT_K_OFF + (it & 1)*ATT_KV_H)*2);
        const unsigned vS = base + (unsigned)((ATT_V_OFF + (it & 1)*ATT_KV_H)*2);
        const float* msp = ms2[it & 1];

        // S = Q K^T (64 compacted keys)
        float ss[8][4] = {};
        #pragma unroll
        for (int dc = 0; dc < 4; dc++) {
            #pragma unroll
            for (int np = 0; np < 4; np++) {
                unsigned bk[4];
                ldsm_x4(bk, kS + kOff + (unsigned)((np*16*AST + dc*16) * 2));
                mma_bf16(ss[2*np],   qf[dc], &bk[0]);
                mma_bf16(ss[2*np+1], qf[dc], &bk[2]);
            }
        }

        // p = 2^(s*SC2 + bias); bias 0 valid / -1e30 padding
        #pragma unroll
        for (int nt = 0; nt < 8; nt++) {
            float b0 = msp[nt*8 + t2], b1 = msp[nt*8 + t2 + 1];
            ss[nt][0] = ex2(ss[nt][0]*SC2 + b0);
            ss[nt][1] = ex2(ss[nt][1]*SC2 + b1);
            ss[nt][2] = ex2(ss[nt][2]*SC2 + b0);
            ss[nt][3] = ex2(ss[nt][3]*SC2 + b1);
            lrun0 += ss[nt][0] + ss[nt][1];
            lrun1 += ss[nt][2] + ss[nt][3];
        }

        // O += P V
        #pragma unroll
        for (int kc = 0; kc < 4; kc++) {
            unsigned ap[4];
            ap[0] = pkbf(ss[2*kc][0],   ss[2*kc][1]);
            ap[1] = pkbf(ss[2*kc][2],   ss[2*kc][3]);
            ap[2] = pkbf(ss[2*kc+1][0], ss[2*kc+1][1]);
            ap[3] = pkbf(ss[2*kc+1][2], ss[2*kc+1][3]);
            #pragma unroll
            for (int p = 0; p < 4; p++) {
                unsigned bv[4];
                ldsm_x4t(bv, vS + vOff + (unsigned)((kc*16*AST + p*16) * 2));
                mma_bf16(o[2*p],   ap, &bv[0]);
                mma_bf16(o[2*p+1], ap, &bv[2]);
            }
        }
        __syncthreads();   // stage (it&1) free for prefetch at it+1
    }

    // epilogue: single cross-lane sum reduction, then normalize + store
    lrun0 += __shfl_xor_sync(0xffffffffu, lrun0, 1);
    lrun0 += __shfl_xor_sync(0xffffffffu, lrun0, 2);
    lrun1 += __shfl_xor_sync(0xffffffffu, lrun1, 1);
    lrun1 += __shfl_xor_sync(0xffffffffu, lrun1, 2);
    float inv0 = 1.0f / lrun0, inv1 = 1.0f / lrun1;
    int r0 = q0 + w*16 + (lane >> 2);
    #pragma unroll
    for (int dt = 0; dt < 8; dt++) {
        int d = dt*8 + t2;
        *(unsigned*)&g_ctx[((size_t)b*SS + r0)*HH + h*HD + d] =
            pkbf(o[dt][0]*inv0, o[dt][1]*inv0);
        *(unsigned*)&g_ctx[((size_t)b*SS + r0 + 8)*HH + h*HD + d] =
            pkbf(o[dt][2]*inv1, o[dt][3]*inv1);
    }
}

// ======================= launch ============================================
extern "C" void kernel_launch(void* const* d_in, const int* in_sizes, int n_in,
                              void* d_out, int out_size)
{
    const float* x      = (const float*)d_in[0];
    const int*   mask   = (const int*)  d_in[1];
    const float* qkv_w  = (const float*)d_in[2];
    const float* qkv_b  = (const float*)d_in[3];
    const float* out_w  = (const float*)d_in[4];
    const float* out_b  = (const float*)d_in[5];
    const float* gamma  = (const float*)d_in[6];
    const float* beta   = (const float*)d_in[7];
    float* out = (float*)d_out;

    cudaFuncSetAttribute(gemm_q_kernel,
                         cudaFuncAttributeMaxDynamicSharedMemorySize, GEMM_SMEM);
    cudaFuncSetAttribute(gemm_kv_kernel,
                         cudaFuncAttributeMaxDynamicSharedMemorySize, GEMM_SMEM);
    cudaFuncSetAttribute(gemm_out_kernel,
                         cudaFuncAttributeMaxDynamicSharedMemorySize, GEMM_SMEM);
    cudaFuncSetAttribute(attn_kernel,
                         cudaFuncAttributeMaxDynamicSharedMemorySize, ATT_SMEM);

    // 0) weights -> bf16; mask compaction
    wcvt_kernel<<<4096, 256>>>(qkv_w, out_w);
    compact_kernel<<<BB, 1024>>>(mask);

    // 1) LayerNorm (f32 -> bf16)
    ln_kernel<<<MM, 256>>>(x, gamma, beta);

    // 2a) Q projection: N=1024, all 8192 rows
    gemm_q_kernel<<<dim3(HH/128, MM/128), 256, GEMM_SMEM>>>(qkv_b);
    // 2b) K+V projection: N=2048, only compacted rows (early-exit per batch)
    gemm_kv_kernel<<<dim3(2*HH/128, BB*16), 256, GEMM_SMEM>>>(qkv_b);

    // 3) attention over compacted keys: 16 q-tiles x 64 (b,h)
    attn_kernel<<<dim3(SS/128, BB*NH), 256, ATT_SMEM>>>();

    // 4) output projection + bias + residual
    gemm_out_kernel<<<dim3(HH/128, MM/128), 256, GEMM_SMEM>>>(out_b, x, out);
}

// round 16
// speedup vs baseline: 1.4880x; 1.0385x over previous
#include <cuda_runtime.h>
#include <cuda_bf16.h>
#include <math.h>

#define BB 4
#define SS 2048
#define HH 1024
#define NH 16
#define HD 64
#define MM (BB*SS)          // 8192 rows

// ---------------- scratch (device globals; no allocation allowed) ----------
__device__ __nv_bfloat16 g_y[BB*SS*HH];        // LN output        16 MB
__device__ __nv_bfloat16 g_q[BB*NH*SS*HD];     // Q [b,h,s,d]      16 MB
__device__ __nv_bfloat16 g_k[BB*NH*SS*HD];     // K [b,h,j,d] compacted
__device__ __nv_bfloat16 g_v[BB*NH*SS*HD];     // V [b,h,j,d] compacted
__device__ __nv_bfloat16 g_ctx[BB*SS*HH];      // attention ctx    16 MB
__device__ __nv_bfloat16 g_wq[3*HH*HH];        // bf16 qkv weights  6 MB
__device__ __nv_bfloat16 g_wo[HH*HH];          // bf16 out weights  2 MB
__device__ int g_idx[BB*SS];                   // compacted unmasked key idx
__device__ int g_cnt[BB];                      // unmasked count per batch

// ---------------- helpers ---------------------------------------------------
__device__ __forceinline__ unsigned pkbf(float lo, float hi) {
    __nv_bfloat162 h = __float22bfloat162_rn(make_float2(lo, hi));
    return *(unsigned*)&h;
}
__device__ __forceinline__ void mma_bf16(float* d, const unsigned* a, const unsigned* b) {
    asm("mma.sync.aligned.m16n8k16.row.col.f32.bf16.bf16.f32 "
        "{%0,%1,%2,%3},{%4,%5,%6,%7},{%8,%9},{%0,%1,%2,%3};"
        : "+f"(d[0]), "+f"(d[1]), "+f"(d[2]), "+f"(d[3])
        : "r"(a[0]), "r"(a[1]), "r"(a[2]), "r"(a[3]), "r"(b[0]), "r"(b[1]));
}
__device__ __forceinline__ void ldsm_x4(unsigned* r, unsigned addr) {
    asm volatile("ldmatrix.sync.aligned.m8n8.x4.shared.b16 {%0,%1,%2,%3},[%4];"
        : "=r"(r[0]), "=r"(r[1]), "=r"(r[2]), "=r"(r[3]) : "r"(addr));
}
__device__ __forceinline__ void ldsm_x4t(unsigned* r, unsigned addr) {
    asm volatile("ldmatrix.sync.aligned.m8n8.x4.trans.shared.b16 {%0,%1,%2,%3},[%4];"
        : "=r"(r[0]), "=r"(r[1]), "=r"(r[2]), "=r"(r[3]) : "r"(addr));
}
__device__ __forceinline__ void cpa16(unsigned dst, const void* src) {
    asm volatile("cp.async.cg.shared.global [%0], [%1], 16;" :: "r"(dst), "l"(src));
}
__device__ __forceinline__ void cpa_commit() {
    asm volatile("cp.async.commit_group;" ::: "memory");
}
template<int N> __device__ __forceinline__ void cpa_wait() {
    asm volatile("cp.async.wait_group %0;" :: "n"(N) : "memory");
}
__device__ __forceinline__ float ex2(float x) {
    float r; asm("ex2.approx.f32 %0, %1;" : "=f"(r) : "f"(x)); return r;
}

// ======================= 0) weight convert (f32 -> bf16) ===================
__global__ void __launch_bounds__(256) wcvt_kernel(
    const float* __restrict__ qw, const float* __restrict__ ow)
{
    const int NQ = 3*HH*HH;
    int i4 = (blockIdx.x*256 + threadIdx.x) * 4;
    if (i4 < NQ) {
        float4 v = *(const float4*)(qw + i4);
        uint2 o; o.x = pkbf(v.x, v.y); o.y = pkbf(v.z, v.w);
        *(uint2*)(g_wq + i4) = o;
    } else {
        float4 v = *(const float4*)(ow + (i4 - NQ));
        uint2 o; o.x = pkbf(v.x, v.y); o.y = pkbf(v.z, v.w);
        *(uint2*)(g_wo + (i4 - NQ)) = o;
    }
}

// ======================= 0b) mask compaction (deterministic scan) ==========
__global__ void __launch_bounds__(1024) compact_kernel(const int* __restrict__ mask)
{
    __shared__ int sc[1024];
    int b = blockIdx.x, t = threadIdx.x;
    int m0 = (mask[b*SS + 2*t]     == 0) ? 1 : 0;
    int m1 = (mask[b*SS + 2*t + 1] == 0) ? 1 : 0;
    sc[t] = m0 + m1;
    __syncthreads();
    #pragma unroll
    for (int off = 1; off < 1024; off <<= 1) {
        int v = (t >= off) ? sc[t - off] : 0;
        __syncthreads();
        sc[t] += v;
        __syncthreads();
    }
    int excl = sc[t] - m0 - m1;
    if (m0) g_idx[b*SS + excl]      = 2*t;
    if (m1) g_idx[b*SS + excl + m0] = 2*t + 1;
    if (t == 1023) g_cnt[b] = sc[1023];
}

// ======================= 1) LayerNorm (f32 in -> bf16 out) =================
__global__ void __launch_bounds__(256) ln_kernel(
    const float* __restrict__ x,
    const float* __restrict__ gamma,
    const float* __restrict__ beta)
{
    int row = blockIdx.x;
    int tid = threadIdx.x;
    const float4 xv = *(const float4*)&x[row*HH + tid*4];

    float s  = xv.x + xv.y + xv.z + xv.w;
    float s2 = xv.x*xv.x + xv.y*xv.y + xv.z*xv.z + xv.w*xv.w;
    #pragma unroll
    for (int o = 16; o > 0; o >>= 1) {
        s  += __shfl_down_sync(0xffffffffu, s,  o);
        s2 += __shfl_down_sync(0xffffffffu, s2, o);
    }
    __shared__ float ss[8], ss2[8];
    if ((tid & 31) == 0) { ss[tid >> 5] = s; ss2[tid >> 5] = s2; }
    __syncthreads();
    float ts = 0.f, ts2 = 0.f;
    #pragma unroll
    for (int w = 0; w < 8; w++) { ts += ss[w]; ts2 += ss2[w]; }

    float mu   = ts * (1.0f / HH);
    float var  = ts2 * (1.0f / HH) - mu * mu;
    float rstd = rsqrtf(var + 1e-5f);

    const float4 gv = *(const float4*)&gamma[tid*4];
    const float4 bv = *(const float4*)&beta[tid*4];
    uint2 o2;
    o2.x = pkbf((xv.x - mu)*rstd*gv.x + bv.x, (xv.y - mu)*rstd*gv.y + bv.y);
    o2.y = pkbf((xv.z - mu)*rstd*gv.z + bv.z, (xv.w - mu)*rstd*gv.w + bv.w);
    *(uint2*)&g_y[row*HH + tid*4] = o2;
}

// ======================= bf16 GEMM (128x128, 8 warps, 64x32 warp tile) =====
// 3-stage cp.async pipeline, k-step 32; per-thread row pointers hoisted.
#define GST      40               // halves; 80B = odd multiple of 16B
#define STAGE_H  (128*GST)        // 5120 halves per operand per stage
#define GSMEM_H  (2*STAGE_H)      // A+B per stage
#define GEMM_SMEM (3*GSMEM_H*2)   // 61440 B

#define GEMM_PREFETCH(kt) do {                                              \
    int s_ = (kt) % 3;                                                      \
    int r_ = tid >> 1;                                                      \
    int h_ = (tid & 1) * 16;                                                \
    unsigned aDst = dsmB + (unsigned)((s_*GSMEM_H + r_*GST + h_) * 2);      \
    unsigned bDst = aDst + STAGE_H*2;                                       \
    const __nv_bfloat16* a_ = Agp + (kt)*32 + h_;                           \
    const __nv_bfloat16* b_ = Bgp + (kt)*32 + h_;                           \
    cpa16(aDst,      a_);                                                   \
    cpa16(aDst + 16, a_ + 8);                                               \
    cpa16(bDst,      b_);                                                   \
    cpa16(bDst + 16, b_ + 8);                                               \
} while (0)

#define GEMM_MAINLOOP(ACC)                                                  \
    GEMM_PREFETCH(0); cpa_commit();                                         \
    GEMM_PREFETCH(1); cpa_commit();                                         \
    const unsigned aOff = (unsigned)(((warp_m + (lane & 15))*GST + (lane >> 4)*8) * 2);            \
    const unsigned bOff = (unsigned)(((warp_n + (lane >> 4)*8 + (lane & 7))*GST + ((lane >> 3) & 1)*8) * 2) + STAGE_H*2; \
    for (int kt = 0; kt < 32; kt++) {                                       \
        cpa_wait<1>();                                                      \
        __syncthreads();                                                    \
        if (kt + 2 < 32) { GEMM_PREFETCH(kt + 2); }                         \
        cpa_commit();                                                       \
        unsigned sB = dsmB + (unsigned)((kt % 3)*GSMEM_H*2);                \
        _Pragma("unroll")                                                   \
        for (int kc = 0; kc < 2; kc++) {                                    \
            unsigned af[4][4], bf[2][4];                                    \
            _Pragma("unroll")                                               \
            for (int mt = 0; mt < 4; mt++)                                  \
                ldsm_x4(af[mt], sB + aOff + (unsigned)((mt*16*GST + kc*16)*2)); \
            _Pragma("unroll")                                               \
            for (int np = 0; np < 2; np++)                                  \
                ldsm_x4(bf[np], sB + bOff + (unsigned)((np*16*GST + kc*16)*2)); \
            _Pragma("unroll")                                               \
            for (int mt = 0; mt < 4; mt++)                                  \
                _Pragma("unroll")                                           \
                for (int np = 0; np < 2; np++) {                            \
                    mma_bf16(ACC[mt][2*np],   af[mt], &bf[np][0]);          \
                    mma_bf16(ACC[mt][2*np+1], af[mt], &bf[np][2]);          \
                }                                                           \
        }                                                                   \
    }

// ---- Fused projection GEMM: flat grid packs Q tiles (id<512) and KV tiles
// (id>=512) into one launch — Q's wave tail fills with KV work, early-exit
// KV tiles vacate immediately. Math identical to the split kernels.
__global__ void __launch_bounds__(256, 2) gemm_proj_kernel(const float* __restrict__ bias)
{
    extern __shared__ __nv_bfloat16 dsm[];
    const int tid = threadIdx.x, lane = tid & 31, w = tid >> 5;
    const int warp_m = (w >> 2) * 64, warp_n = (w & 3) * 32;
    const int id = blockIdx.x;
    const unsigned dsmB = (unsigned)__cvta_generic_to_shared(dsm);

    const __nv_bfloat16 *Agp, *Bgp;
    int n0, m0, b_kv = 0;
    const bool isQ = (id < 512);
    if (isQ) {
        n0 = (id & 7) * 128;               // 8 n-tiles over N=1024
        m0 = (id >> 3) * 128;              // 64 m-tiles over M=8192
        Agp = g_y  + (size_t)(m0 + (tid >> 1)) * HH;
        Bgp = g_wq + (size_t)(n0 + (tid >> 1)) * HH;
    } else {
        int id2 = id - 512;
        n0 = (id2 & 15) * 128;             // 16 n-tiles over N=2048 (K|V)
        int yk = id2 >> 4;                 // 64 = 4 batches x 16 m-tiles
        b_kv = yk >> 4;
        m0 = (yk & 15) * 128;
        const int cnt = g_cnt[b_kv];
        if (m0 >= cnt) return;             // uniform per block
        int j = m0 + (tid >> 1);
        int srow = g_idx[b_kv*SS + ((j < cnt) ? j : 0)];
        Agp = g_y  + (size_t)(b_kv*SS + srow) * HH;
        Bgp = g_wq + (size_t)(HH + n0 + (tid >> 1)) * HH;
    }

    float acc[4][4][4] = {};
    GEMM_MAINLOOP(acc)

    const int g = lane >> 2, t2 = (lane & 3) * 2;
    if (isQ) {
        #pragma unroll
        for (int nt = 0; nt < 4; nt++) {
            int gn = n0 + warp_n + nt*8 + t2;
            int head = (gn >> 6) & 15, d = gn & 63;
            float2 bi = *(const float2*)&bias[gn];
            #pragma unroll
            for (int mt = 0; mt < 4; mt++) {
                int m = m0 + warp_m + mt*16 + g;
                int b = m >> 11, s = m & 2047;
                __nv_bfloat16* p = &g_q[((size_t)(b*NH + head)*SS + s)*HD + d];
                *(unsigned*)p          = pkbf(acc[mt][nt][0] + bi.x, acc[mt][nt][1] + bi.y);
                *(unsigned*)(p + 8*HD) = pkbf(acc[mt][nt][2] + bi.x, acc[mt][nt][3] + bi.y);
            }
        }
    } else {
        #pragma unroll
        for (int nt = 0; nt < 4; nt++) {
            int gn = n0 + warp_n + nt*8 + t2;      // 0..2047: K then V
            int grp = gn >> 10, head = (gn >> 6) & 15, d = gn & 63;
            __nv_bfloat16* dst = (grp == 0) ? g_k : g_v;
            float2 bi = *(const float2*)&bias[HH + gn];
            #pragma unroll
            for (int mt = 0; mt < 4; mt++) {
                int jj = m0 + warp_m + mt*16 + g;  // compacted slot
                __nv_bfloat16* p = &dst[((size_t)(b_kv*NH + head)*SS + jj)*HD + d];
                *(unsigned*)p          = pkbf(acc[mt][nt][0] + bi.x, acc[mt][nt][1] + bi.y);
                *(unsigned*)(p + 8*HD) = pkbf(acc[mt][nt][2] + bi.x, acc[mt][nt][3] + bi.y);
            }
        }
    }
}

// ---- Output GEMM: + bias + residual (f32 out) -----------------------------
__global__ void __launch_bounds__(256, 2) gemm_out_kernel(
    const float* __restrict__ bias,
    const float* __restrict__ x,
    float* __restrict__ out)
{
    extern __shared__ __nv_bfloat16 dsm[];
    const int tid = threadIdx.x, lane = tid & 31, w = tid >> 5;
    const int warp_m = (w >> 2) * 64, warp_n = (w & 3) * 32;
    const int n0 = blockIdx.x * 128, m0 = blockIdx.y * 128;
    const __nv_bfloat16* Agp = g_ctx + (size_t)(m0 + (tid >> 1)) * HH;
    const __nv_bfloat16* Bgp = g_wo  + (size_t)(n0 + (tid >> 1)) * HH;
    const unsigned dsmB = (unsigned)__cvta_generic_to_shared(dsm);

    float acc[4][4][4] = {};
    GEMM_MAINLOOP(acc)

    const int g = lane >> 2, t2 = (lane & 3) * 2;
    #pragma unroll
    for (int nt = 0; nt < 4; nt++) {
        int gn = n0 + warp_n + nt*8 + t2;
        float2 bi = *(const float2*)&bias[gn];
        #pragma unroll
        for (int mt = 0; mt < 4; mt++) {
            int m = m0 + warp_m + mt*16 + g;
            const float2 x0 = *(const float2*)&x[(size_t)m*HH + gn];
            const float2 x1 = *(const float2*)&x[(size_t)(m+8)*HH + gn];
            float2 v0 = {acc[mt][nt][0] + bi.x + x0.x, acc[mt][nt][1] + bi.y + x0.y};
            float2 v1 = {acc[mt][nt][2] + bi.x + x1.x, acc[mt][nt][3] + bi.y + x1.y};
            *(float2*)&out[(size_t)m*HH + gn]     = v0;
            *(float2*)&out[(size_t)(m+8)*HH + gn] = v1;
        }
    }
}

// ======================= 3) Flash attention over COMPACTED K/V =============
#define AST 72
#define ATT_KV_H   (64*AST)
#define ATT_K_OFF  (128*AST)
#define ATT_V_OFF  (128*AST + 2*ATT_KV_H)
#define ATT_SMEM   ((128*AST + 4*ATT_KV_H)*2)   // 55296 B
#define LOG2E 1.44269504f

#define ATT_PREFETCH(it) do {                                               \
    int s_ = (it) & 1;                                                      \
    int r_ = tid >> 2;                                                      \
    int ch_ = (tid & 3) * 2;                                                \
    unsigned kDst = base + (unsigned)((ATT_K_OFF + s_*ATT_KV_H + r_*AST)*2); \
    unsigned vDst = base + (unsigned)((ATT_V_OFF + s_*ATT_KV_H + r_*AST)*2); \
    const __nv_bfloat16* kp = Kg + (size_t)((it)*64 + r_)*HD;               \
    const __nv_bfloat16* vp = Vg + (size_t)((it)*64 + r_)*HD;               \
    _Pragma("unroll")                                                       \
    for (int c_ = 0; c_ < 2; c_++) {                                        \
        cpa16(kDst + (ch_ + c_)*16, kp + (ch_ + c_)*8);                     \
        cpa16(vDst + (ch_ + c_)*16, vp + (ch_ + c_)*8);                     \
    }                                                                       \
    if (tid < 64) ms2[s_][tid] = ((it)*64 + tid < ncnt) ? 0.f : -1e30f;     \
} while (0)

__global__ void __launch_bounds__(256, 2) attn_kernel(void)
{
    extern __shared__ __nv_bfloat16 smp[];
    __shared__ float ms2[2][64];

    const int tid  = threadIdx.x;
    const int lane = tid & 31;
    const int w    = tid >> 5;
    const int bh = blockIdx.y;
    const int q0 = blockIdx.x * 128;
    const int b  = bh >> 4, h = bh & 15;

    const __nv_bfloat16* Qg = g_q + (size_t)bh * SS * HD;
    const __nv_bfloat16* Kg = g_k + (size_t)bh * SS * HD;
    const __nv_bfloat16* Vg = g_v + (size_t)bh * SS * HD;
    const int  ncnt = g_cnt[b];
    const int  nt_total = (ncnt + 63) >> 6;

    const unsigned base = (unsigned)__cvta_generic_to_shared(smp);

    {
        int r = tid >> 1, c0 = (tid & 1) * 32;
        #pragma unroll
        for (int i = 0; i < 4; i++)
            *(uint4*)&smp[r*AST + c0 + i*8] =
                *(const uint4*)&Qg[(size_t)(q0 + r)*HD + c0 + i*8];
    }
    ATT_PREFETCH(0);
    cpa_commit();
    __syncthreads();

    const unsigned qBase = base + (unsigned)(((w*16 + (lane & 15))*AST + (lane >> 4)*8) * 2);
    unsigned qf[4][4];
    #pragma unroll
    for (int dc = 0; dc < 4; dc++)
        ldsm_x4(qf[dc], qBase + (unsigned)(dc*16*2));

    const unsigned kOff = (unsigned)((((lane >> 4)*8 + (lane & 7))*AST + ((lane >> 3) & 1)*8) * 2);
    const unsigned vOff = (unsigned)(((((lane >> 3) & 1)*8 + (lane & 7))*AST + (lane >> 4)*8) * 2);

    float o[8][4] = {};
    float lrun0 = 0.f, lrun1 = 0.f;
    const int t2 = (lane & 3) * 2;
    const float SC2 = 0.125f * LOG2E;

    for (int it = 0; it < nt_total; it++) {
        if (it + 1 < nt_total) { ATT_PREFETCH(it + 1); }
        cpa_commit();
        cpa_wait<1>();
        __syncthreads();

        const unsigned kS = base + (unsigned)((ATT_K_OFF + (it & 1)*ATT_KV_H)*2);
        const unsigned vS = base + (unsigned)((ATT_V_OFF + (it & 1)*ATT_KV_H)*2);
        const float* msp = ms2[it & 1];

        float ss[8][4] = {};
        #pragma unroll
        for (int dc = 0; dc < 4; dc++) {
            #pragma unroll
            for (int np = 0; np < 4; np++) {
                unsigned bk[4];
                ldsm_x4(bk, kS + kOff + (unsigned)((np*16*AST + dc*16) * 2));
                mma_bf16(ss[2*np],   qf[dc], &bk[0]);
                mma_bf16(ss[2*np+1], qf[dc], &bk[2]);
            }
        }

        #pragma unroll
        for (int nt = 0; nt < 8; nt++) {
            float b0 = msp[nt*8 + t2], b1 = msp[nt*8 + t2 + 1];
            ss[nt][0] = ex2(ss[nt][0]*SC2 + b0);
            ss[nt][1] = ex2(ss[nt][1]*SC2 + b1);
            ss[nt][2] = ex2(ss[nt][2]*SC2 + b0);
            ss[nt][3] = ex2(ss[nt][3]*SC2 + b1);
            lrun0 += ss[nt][0] + ss[nt][1];
            lrun1 += ss[nt][2] + ss[nt][3];
        }

        #pragma unroll
        for (int kc = 0; kc < 4; kc++) {
            unsigned ap[4];
            ap[0] = pkbf(ss[2*kc][0],   ss[2*kc][1]);
            ap[1] = pkbf(ss[2*kc][2],   ss[2*kc][3]);
            ap[2] = pkbf(ss[2*kc+1][0], ss[2*kc+1][1]);
            ap[3] = pkbf(ss[2*kc+1][2], ss[2*kc+1][3]);
            #pragma unroll
            for (int p = 0; p < 4; p++) {
                unsigned bv[4];
                ldsm_x4t(bv, vS + vOff + (unsigned)((kc*16*AST + p*16) * 2));
                mma_bf16(o[2*p],   ap, &bv[0]);
                mma_bf16(o[2*p+1], ap, &bv[2]);
            }
        }
        __syncthreads();
    }

    lrun0 += __shfl_xor_sync(0xffffffffu, lrun0, 1);
    lrun0 += __shfl_xor_sync(0xffffffffu, lrun0, 2);
    lrun1 += __shfl_xor_sync(0xffffffffu, lrun1, 1);
    lrun1 += __shfl_xor_sync(0xffffffffu, lrun1, 2);
    float inv0 = 1.0f / lrun0, inv1 = 1.0f / lrun1;
    int r0 = q0 + w*16 + (lane >> 2);
    #pragma unroll
    for (int dt = 0; dt < 8; dt++) {
        int d = dt*8 + t2;
        *(unsigned*)&g_ctx[((size_t)b*SS + r0)*HH + h*HD + d] =
            pkbf(o[dt][0]*inv0, o[dt][1]*inv0);
        *(unsigned*)&g_ctx[((size_t)b*SS + r0 + 8)*HH + h*HD + d] =
            pkbf(o[dt][2]*inv1, o[dt][3]*inv1);
    }
}

// ======================= launch ============================================
extern "C" void kernel_launch(void* const* d_in, const int* in_sizes, int n_in,
                              void* d_out, int out_size)
{
    const float* x      = (const float*)d_in[0];
    const int*   mask   = (const int*)  d_in[1];
    const float* qkv_w  = (const float*)d_in[2];
    const float* qkv_b  = (const float*)d_in[3];
    const float* out_w  = (const float*)d_in[4];
    const float* out_b  = (const float*)d_in[5];
    const float* gamma  = (const float*)d_in[6];
    const float* beta   = (const float*)d_in[7];
    float* out = (float*)d_out;

    cudaFuncSetAttribute(gemm_proj_kernel,
                         cudaFuncAttributeMaxDynamicSharedMemorySize, GEMM_SMEM);
    cudaFuncSetAttribute(gemm_out_kernel,
                         cudaFuncAttributeMaxDynamicSharedMemorySize, GEMM_SMEM);
    cudaFuncSetAttribute(attn_kernel,
                         cudaFuncAttributeMaxDynamicSharedMemorySize, ATT_SMEM);

    // 0) weights -> bf16; mask compaction
    wcvt_kernel<<<4096, 256>>>(qkv_w, out_w);
    compact_kernel<<<BB, 1024>>>(mask);

    // 1) LayerNorm (f32 -> bf16)
    ln_kernel<<<MM, 256>>>(x, gamma, beta);

    // 2) fused Q + compacted-KV projection (one launch, 1536 tiles)
    gemm_proj_kernel<<<1536, 256, GEMM_SMEM>>>(qkv_b);

    // 3) attention over compacted keys: 16 q-tiles x 64 (b,h)
    attn_kernel<<<dim3(SS/128, BB*NH), 256, ATT_SMEM>>>();

    // 4) output projection + bias + residual
    gemm_out_kernel<<<dim3(HH/128, MM/128), 256, GEMM_SMEM>>>(out_b, x, out);
}